// round 2
// baseline (speedup 1.0000x reference)
#include <cuda_runtime.h>
#include <cuda_bf16.h>
#include <cstddef>

// Problem constants: N=50000, DEG=32, E=N*32, F=64, K=3, DIM=2, L=3
#define MAXN 50000
#define FDIM 64
#define KKER 3
#define KF   192   // K * F

// Scratch (device globals — no allocation allowed in kernel_launch)
__device__ float g_buf[(size_t)MAXN * KF];        // aggregated [N, K*F]
__device__ float h_bufA[(size_t)MAXN * FDIM];
__device__ float h_bufB[(size_t)MAXN * FDIM];

// ---------------------------------------------------------------------------
// Aggregation kernel: one warp per destination node.
//   g[i, k*64 + f] = sum_{e in [rowptr[i], rowptr[i+1])} w_k(e) * h[colind[e], f]
// ---------------------------------------------------------------------------
__global__ __launch_bounds__(256)
void agg_kernel(const float* __restrict__ h,
                const float* __restrict__ pseudo,   // [E,2]
                const int*   __restrict__ rowptr,   // [N+1]
                const int*   __restrict__ colind,   // [E]
                const float* __restrict__ pW,       // [2,2]
                const float* __restrict__ pb,       // [2]
                const float* __restrict__ mu,       // [K,2]
                const float* __restrict__ isg,      // [K,2]
                float* __restrict__ g, int n)
{
    __shared__ float w0s[8][32], w1s[8][32], w2s[8][32];
    __shared__ int   ss[8][32];

    const int wid = threadIdx.x >> 5;
    const int lid = threadIdx.x & 31;
    const int node = blockIdx.x * 8 + wid;
    if (node >= n) return;

    const float W00 = pW[0], W01 = pW[1], W10 = pW[2], W11 = pW[3];
    const float b0 = pb[0], b1 = pb[1];
    const float m00 = mu[0], m01 = mu[1], m10 = mu[2], m11 = mu[3], m20 = mu[4], m21 = mu[5];
    const float s00 = isg[0]*isg[0], s01 = isg[1]*isg[1];
    const float s10 = isg[2]*isg[2], s11 = isg[3]*isg[3];
    const float s20 = isg[4]*isg[4], s21 = isg[5]*isg[5];

    const int e0 = rowptr[node], e1 = rowptr[node + 1];

    float a0x = 0.f, a0y = 0.f, a1x = 0.f, a1y = 0.f, a2x = 0.f, a2y = 0.f;
    const float2* __restrict__ ps2 = (const float2*)pseudo;

    for (int base = e0; base < e1; base += 32) {
        const int cnt = min(32, e1 - base);
        if (lid < cnt) {
            const int e = base + lid;
            float2 ps = __ldg(&ps2[e]);
            float u0 = tanhf(fmaf(ps.y, W10, fmaf(ps.x, W00, b0)));
            float u1 = tanhf(fmaf(ps.y, W11, fmaf(ps.x, W01, b1)));
            float d0, d1;
            d0 = u0 - m00; d1 = u1 - m01;
            w0s[wid][lid] = __expf(-0.5f * (d0*d0*s00 + d1*d1*s01));
            d0 = u0 - m10; d1 = u1 - m11;
            w1s[wid][lid] = __expf(-0.5f * (d0*d0*s10 + d1*d1*s11));
            d0 = u0 - m20; d1 = u1 - m21;
            w2s[wid][lid] = __expf(-0.5f * (d0*d0*s20 + d1*d1*s21));
            ss[wid][lid] = __ldg(&colind[e]);
        }
        __syncwarp();
        if (cnt == 32) {
            #pragma unroll 8
            for (int t = 0; t < 32; t++) {
                const float2 hv = __ldg((const float2*)(h + (size_t)ss[wid][t] * FDIM) + lid);
                const float w0 = w0s[wid][t], w1 = w1s[wid][t], w2 = w2s[wid][t];
                a0x = fmaf(w0, hv.x, a0x); a0y = fmaf(w0, hv.y, a0y);
                a1x = fmaf(w1, hv.x, a1x); a1y = fmaf(w1, hv.y, a1y);
                a2x = fmaf(w2, hv.x, a2x); a2y = fmaf(w2, hv.y, a2y);
            }
        } else {
            for (int t = 0; t < cnt; t++) {
                const float2 hv = __ldg((const float2*)(h + (size_t)ss[wid][t] * FDIM) + lid);
                const float w0 = w0s[wid][t], w1 = w1s[wid][t], w2 = w2s[wid][t];
                a0x = fmaf(w0, hv.x, a0x); a0y = fmaf(w0, hv.y, a0y);
                a1x = fmaf(w1, hv.x, a1x); a1y = fmaf(w1, hv.y, a1y);
                a2x = fmaf(w2, hv.x, a2x); a2y = fmaf(w2, hv.y, a2y);
            }
        }
        __syncwarp();
    }

    const size_t o = (size_t)node * KF;
    ((float2*)(g + o      ))[lid] = make_float2(a0x, a0y);
    ((float2*)(g + o +  64))[lid] = make_float2(a1x, a1y);
    ((float2*)(g + o + 128))[lid] = make_float2(a2x, a2y);
}

// ---------------------------------------------------------------------------
// GEMM kernel: out[i,f] = sum_p g[i,p] * Wk[p,f]   (Wk[p=k*64+j][f] = fcW[j*192+k*64+f])
// Persistent. 256 threads, block tile 64 rows x 64 cols, thread tile 4x4.
// smem: Ws[192][64] (48KB) + gsT[192][64] transposed g tile (48KB) = 96KB
// -> 2 CTAs/SM (192KB < 227KB), 16 warps/SM. Inner loop: 2x LDS.128 + 16 FFMA.
// ---------------------------------------------------------------------------
#define GEMM_SMEM (2 * 192 * 64 * 4)   // 98304 bytes

__global__ __launch_bounds__(256, 2)
void gemm_kernel(const float* __restrict__ g,   // [n, 192]
                 const float* __restrict__ W,   // [64, 192]
                 float* __restrict__ out, int n)
{
    extern __shared__ float smem[];
    float* Ws  = smem;              // [192][64]  Ws[p*64+f]
    float* gsT = smem + 192 * 64;   // [192][64]  gsT[p*64+r]

    const int tid = threadIdx.x;

    // Load weights once: Ws[p][f], p = k*64 + j -> W[j*192 + k*64 + f]
    for (int idx = tid; idx < 192 * 64; idx += 256) {
        const int p = idx >> 6, f = idx & 63;
        const int j = p & 63, k = p >> 6;
        Ws[idx] = __ldg(&W[j * 192 + k * 64 + f]);
    }

    const int tx = tid & 15;   // col group: cols tx*4 .. +3
    const int ty = tid >> 4;   // row group: rows ty*4 .. +3

    const int ntiles = (n + 63) >> 6;
    for (int tile = blockIdx.x; tile < ntiles; tile += gridDim.x) {
        const int r0 = tile << 6;
        const int rows = min(64, n - r0);

        // Load g tile transposed: each idx = one float4 of a row
        for (int idx = tid; idx < 64 * 48; idx += 256) {
            const int r = idx / 48, pc = idx - r * 48;   // pc: float4 index in row
            float4 v = make_float4(0.f, 0.f, 0.f, 0.f);
            if (r < rows)
                v = __ldg((const float4*)(g + (size_t)(r0 + r) * KF) + pc);
            const int p = pc * 4;
            gsT[(p    ) * 64 + r] = v.x;
            gsT[(p + 1) * 64 + r] = v.y;
            gsT[(p + 2) * 64 + r] = v.z;
            gsT[(p + 3) * 64 + r] = v.w;
        }
        __syncthreads();

        float acc[4][4];
        #pragma unroll
        for (int i = 0; i < 4; i++)
            #pragma unroll
            for (int j = 0; j < 4; j++) acc[i][j] = 0.f;

        #pragma unroll 2
        for (int p = 0; p < 192; p++) {
            const float4 gv = *(const float4*)&gsT[p * 64 + ty * 4];
            const float4 wv = *(const float4*)&Ws [p * 64 + tx * 4];
            acc[0][0] = fmaf(gv.x, wv.x, acc[0][0]);
            acc[0][1] = fmaf(gv.x, wv.y, acc[0][1]);
            acc[0][2] = fmaf(gv.x, wv.z, acc[0][2]);
            acc[0][3] = fmaf(gv.x, wv.w, acc[0][3]);
            acc[1][0] = fmaf(gv.y, wv.x, acc[1][0]);
            acc[1][1] = fmaf(gv.y, wv.y, acc[1][1]);
            acc[1][2] = fmaf(gv.y, wv.z, acc[1][2]);
            acc[1][3] = fmaf(gv.y, wv.w, acc[1][3]);
            acc[2][0] = fmaf(gv.z, wv.x, acc[2][0]);
            acc[2][1] = fmaf(gv.z, wv.y, acc[2][1]);
            acc[2][2] = fmaf(gv.z, wv.z, acc[2][2]);
            acc[2][3] = fmaf(gv.z, wv.w, acc[2][3]);
            acc[3][0] = fmaf(gv.w, wv.x, acc[3][0]);
            acc[3][1] = fmaf(gv.w, wv.y, acc[3][1]);
            acc[3][2] = fmaf(gv.w, wv.z, acc[3][2]);
            acc[3][3] = fmaf(gv.w, wv.w, acc[3][3]);
        }

        #pragma unroll
        for (int i = 0; i < 4; i++) {
            const int r = ty * 4 + i;
            if (r < rows) {
                float4 o4 = make_float4(acc[i][0], acc[i][1], acc[i][2], acc[i][3]);
                *(float4*)&out[(size_t)(r0 + r) * FDIM + tx * 4] = o4;
            }
        }
        __syncthreads();
    }
}

// ---------------------------------------------------------------------------
extern "C" void kernel_launch(void* const* d_in, const int* in_sizes, int n_in,
                              void* d_out, int out_size)
{
    const float* feat   = (const float*)d_in[0];
    const float* pseudo = (const float*)d_in[1];
    const int*   rowptr = (const int*)  d_in[2];
    const int*   colind = (const int*)  d_in[3];
    const float* projW  = (const float*)d_in[4];  // [L,2,2]
    const float* projb  = (const float*)d_in[5];  // [L,2]
    const float* fcW    = (const float*)d_in[6];  // [L,64,192]
    const float* mu     = (const float*)d_in[7];  // [L,3,2]
    const float* isg    = (const float*)d_in[8];  // [L,3,2]

    const int n  = in_sizes[0] / FDIM;
    const int nL = in_sizes[6] / (FDIM * KF);

    void *gp, *hap, *hbp;
    cudaGetSymbolAddress(&gp,  g_buf);
    cudaGetSymbolAddress(&hap, h_bufA);
    cudaGetSymbolAddress(&hbp, h_bufB);
    float* gbuf = (float*)gp;
    float* hbufs[2] = { (float*)hap, (float*)hbp };

    cudaFuncSetAttribute(gemm_kernel, cudaFuncAttributeMaxDynamicSharedMemorySize, GEMM_SMEM);

    const int aggGrid = (n + 7) / 8;
    const int ntiles  = (n + 63) / 64;
    const int gemmGrid = ntiles < 296 ? ntiles : 296;   // 2 CTAs/SM persistent

    const float* hin = feat;
    for (int i = 0; i < nL; i++) {
        float* hout = (i == nL - 1) ? (float*)d_out : hbufs[i & 1];
        agg_kernel<<<aggGrid, 256>>>(hin, pseudo, rowptr, colind,
                                     projW + i * 4, projb + i * 2,
                                     mu + i * 6, isg + i * 6,
                                     gbuf, n);
        gemm_kernel<<<gemmGrid, 256, GEMM_SMEM>>>(gbuf, fcW + i * (FDIM * KF), hout, n);
        hin = hout;
    }
}

// round 3
// speedup vs baseline: 1.4696x; 1.4696x over previous
#include <cuda_runtime.h>
#include <cuda_bf16.h>
#include <cstddef>

// Problem constants: N=50000, DEG=32, E=N*32, F=64, K=3, DIM=2, L=3
#define MAXN 50000
#define FDIM 64
#define KKER 3
#define KF   192   // K * F

// Scratch (device globals — no allocation allowed in kernel_launch)
__device__ float g_buf[(size_t)MAXN * KF];        // aggregated [N, K*F]
__device__ float h_bufA[(size_t)MAXN * FDIM];
__device__ float h_bufB[(size_t)MAXN * FDIM];

// Packed fp32x2 FMA (sm_103a FFMA2 — only reachable via PTX)
#define FMA_F32X2(d, a, b, c) \
    asm("fma.rn.f32x2 %0, %1, %2, %3;" : "=l"(d) : "l"(a), "l"(b), "l"(c))
#define PACK_DUP(d, x) \
    asm("mov.b64 %0, {%1, %1};" : "=l"(d) : "f"(x))
#define UNPACK2(lo, hi, v) \
    asm("mov.b64 {%0, %1}, %2;" : "=f"(lo), "=f"(hi) : "l"(v))

// ---------------------------------------------------------------------------
// Aggregation kernel: one warp per destination node.
//   g[i, k*64 + f] = sum_{e in [rowptr[i], rowptr[i+1])} w_k(e) * h[colind[e], f]
// ---------------------------------------------------------------------------
__global__ __launch_bounds__(256)
void agg_kernel(const float* __restrict__ h,
                const float* __restrict__ pseudo,   // [E,2]
                const int*   __restrict__ rowptr,   // [N+1]
                const int*   __restrict__ colind,   // [E]
                const float* __restrict__ pW,       // [2,2]
                const float* __restrict__ pb,       // [2]
                const float* __restrict__ mu,       // [K,2]
                const float* __restrict__ isg,      // [K,2]
                float* __restrict__ g, int n)
{
    __shared__ float w0s[8][32], w1s[8][32], w2s[8][32];
    __shared__ int   ss[8][32];

    const int wid = threadIdx.x >> 5;
    const int lid = threadIdx.x & 31;
    const int node = blockIdx.x * 8 + wid;
    if (node >= n) return;

    const float W00 = pW[0], W01 = pW[1], W10 = pW[2], W11 = pW[3];
    const float b0 = pb[0], b1 = pb[1];
    const float m00 = mu[0], m01 = mu[1], m10 = mu[2], m11 = mu[3], m20 = mu[4], m21 = mu[5];
    const float s00 = isg[0]*isg[0], s01 = isg[1]*isg[1];
    const float s10 = isg[2]*isg[2], s11 = isg[3]*isg[3];
    const float s20 = isg[4]*isg[4], s21 = isg[5]*isg[5];

    const int e0 = rowptr[node], e1 = rowptr[node + 1];

    float a0x = 0.f, a0y = 0.f, a1x = 0.f, a1y = 0.f, a2x = 0.f, a2y = 0.f;
    const float2* __restrict__ ps2 = (const float2*)pseudo;

    for (int base = e0; base < e1; base += 32) {
        const int cnt = min(32, e1 - base);
        if (lid < cnt) {
            const int e = base + lid;
            float2 ps = __ldg(&ps2[e]);
            float u0 = tanhf(fmaf(ps.y, W10, fmaf(ps.x, W00, b0)));
            float u1 = tanhf(fmaf(ps.y, W11, fmaf(ps.x, W01, b1)));
            float d0, d1;
            d0 = u0 - m00; d1 = u1 - m01;
            w0s[wid][lid] = __expf(-0.5f * (d0*d0*s00 + d1*d1*s01));
            d0 = u0 - m10; d1 = u1 - m11;
            w1s[wid][lid] = __expf(-0.5f * (d0*d0*s10 + d1*d1*s11));
            d0 = u0 - m20; d1 = u1 - m21;
            w2s[wid][lid] = __expf(-0.5f * (d0*d0*s20 + d1*d1*s21));
            ss[wid][lid] = __ldg(&colind[e]);
        }
        __syncwarp();
        if (cnt == 32) {
            #pragma unroll 8
            for (int t = 0; t < 32; t++) {
                const float2 hv = __ldg((const float2*)(h + (size_t)ss[wid][t] * FDIM) + lid);
                const float w0 = w0s[wid][t], w1 = w1s[wid][t], w2 = w2s[wid][t];
                a0x = fmaf(w0, hv.x, a0x); a0y = fmaf(w0, hv.y, a0y);
                a1x = fmaf(w1, hv.x, a1x); a1y = fmaf(w1, hv.y, a1y);
                a2x = fmaf(w2, hv.x, a2x); a2y = fmaf(w2, hv.y, a2y);
            }
        } else {
            for (int t = 0; t < cnt; t++) {
                const float2 hv = __ldg((const float2*)(h + (size_t)ss[wid][t] * FDIM) + lid);
                const float w0 = w0s[wid][t], w1 = w1s[wid][t], w2 = w2s[wid][t];
                a0x = fmaf(w0, hv.x, a0x); a0y = fmaf(w0, hv.y, a0y);
                a1x = fmaf(w1, hv.x, a1x); a1y = fmaf(w1, hv.y, a1y);
                a2x = fmaf(w2, hv.x, a2x); a2y = fmaf(w2, hv.y, a2y);
            }
        }
        __syncwarp();
    }

    const size_t o = (size_t)node * KF;
    ((float2*)(g + o      ))[lid] = make_float2(a0x, a0y);
    ((float2*)(g + o +  64))[lid] = make_float2(a1x, a1y);
    ((float2*)(g + o + 128))[lid] = make_float2(a2x, a2y);
}

// ---------------------------------------------------------------------------
// GEMM: out[i,f] = sum_p g[i,p] * Wk[p,f]   (Wk[p=k*64+j][f] = fcW[j*192+k*64+f])
// Persistent, 384 threads, block tile 192 rows x 64 cols, thread tile 8x4.
// smem: Ws[192][64] (48KB) + gsT[192][192] transposed+swizzled (144KB) = 192KB.
// Inner loop uses packed fma.rn.f32x2 pairing ADJACENT ROWS (contiguous in
// the transposed tile -> packed g operand is a plain 8B shared load).
// Transpose store swizzle: rsw = r ^ ((pc&7)<<2) -> 8-bank spread.
// ---------------------------------------------------------------------------
#define TROWS 192
#define GEMM_SMEM ((192 * 64 + 192 * TROWS) * 4)   // 196608 bytes

__global__ __launch_bounds__(384, 1)
void gemm_kernel(const float* __restrict__ g,   // [n, 192]
                 const float* __restrict__ W,   // [64, 192]
                 float* __restrict__ out, int n)
{
    extern __shared__ float smem[];
    float* Ws  = smem;               // [192][64]   Ws[p*64+f]
    float* gsT = smem + 192 * 64;    // [192][192]  gsT[p*TROWS + swizzle(r)]

    const int tid = threadIdx.x;

    // Load weights once: Ws[p][f], p = k*64 + j -> W[j*192 + k*64 + f]
    for (int idx = tid; idx < 192 * 64; idx += 384) {
        const int p = idx >> 6, f = idx & 63;
        const int j = p & 63, k = p >> 6;
        Ws[idx] = __ldg(&W[j * 192 + k * 64 + f]);
    }

    const int tx = tid & 15;        // f group: cols tx*4..+3
    const int ty = tid >> 4;        // row group (0..23): rows ty*8..+7
    const int ty8 = ty << 3;

    const int ntiles = (n + TROWS - 1) / TROWS;
    for (int tile = blockIdx.x; tile < ntiles; tile += gridDim.x) {
        const int r0 = tile * TROWS;
        const int rows = min(TROWS, n - r0);
        __syncthreads();   // prev-iteration readers done (and Ws ready on iter 0)

        // Transposed load: idx walks (row, float4-chunk). Swizzled store.
        for (int idx = tid; idx < TROWS * 48; idx += 384) {
            const int r = idx / 48, pc = idx - r * 48;
            float4 v = make_float4(0.f, 0.f, 0.f, 0.f);
            if (r < rows)
                v = __ldg((const float4*)(g + (size_t)(r0 + r) * KF) + pc);
            const int rsw = r ^ ((pc & 7) << 2);
            const int p = pc << 2;
            gsT[(p    ) * TROWS + rsw] = v.x;
            gsT[(p + 1) * TROWS + rsw] = v.y;
            gsT[(p + 2) * TROWS + rsw] = v.z;
            gsT[(p + 3) * TROWS + rsw] = v.w;
        }
        __syncthreads();

        // acc[rp][c] = packed {out[ty8+2rp][tx*4+c], out[ty8+2rp+1][tx*4+c]}
        unsigned long long acc[4][4];
        #pragma unroll
        for (int i = 0; i < 4; i++)
            #pragma unroll
            for (int j = 0; j < 4; j++) acc[i][j] = 0ULL;

        #pragma unroll 4
        for (int p = 0; p < 192; p++) {
            const int c  = ((p >> 2) & 7) << 2;
            const int b0 = ty8 ^ c;          // swizzled index of rows ty8..+3
            const int b1 = b0 ^ 4;           // swizzled index of rows ty8+4..+7
            const ulonglong2 ga = *(const ulonglong2*)(gsT + p * TROWS + b0);
            const ulonglong2 gb = *(const ulonglong2*)(gsT + p * TROWS + b1);
            const float4 wv = *(const float4*)(Ws + p * 64 + (tx << 2));
            unsigned long long w0, w1, w2, w3;
            PACK_DUP(w0, wv.x); PACK_DUP(w1, wv.y);
            PACK_DUP(w2, wv.z); PACK_DUP(w3, wv.w);

            FMA_F32X2(acc[0][0], ga.x, w0, acc[0][0]);
            FMA_F32X2(acc[0][1], ga.x, w1, acc[0][1]);
            FMA_F32X2(acc[0][2], ga.x, w2, acc[0][2]);
            FMA_F32X2(acc[0][3], ga.x, w3, acc[0][3]);
            FMA_F32X2(acc[1][0], ga.y, w0, acc[1][0]);
            FMA_F32X2(acc[1][1], ga.y, w1, acc[1][1]);
            FMA_F32X2(acc[1][2], ga.y, w2, acc[1][2]);
            FMA_F32X2(acc[1][3], ga.y, w3, acc[1][3]);
            FMA_F32X2(acc[2][0], gb.x, w0, acc[2][0]);
            FMA_F32X2(acc[2][1], gb.x, w1, acc[2][1]);
            FMA_F32X2(acc[2][2], gb.x, w2, acc[2][2]);
            FMA_F32X2(acc[2][3], gb.x, w3, acc[2][3]);
            FMA_F32X2(acc[3][0], gb.y, w0, acc[3][0]);
            FMA_F32X2(acc[3][1], gb.y, w1, acc[3][1]);
            FMA_F32X2(acc[3][2], gb.y, w2, acc[3][2]);
            FMA_F32X2(acc[3][3], gb.y, w3, acc[3][3]);
        }

        // Epilogue: unpack row pairs, store float4 per row.
        #pragma unroll
        for (int rp = 0; rp < 4; rp++) {
            float lx, hx, ly, hy, lz, hz, lw, hw;
            UNPACK2(lx, hx, acc[rp][0]);
            UNPACK2(ly, hy, acc[rp][1]);
            UNPACK2(lz, hz, acc[rp][2]);
            UNPACK2(lw, hw, acc[rp][3]);
            const int rA = ty8 + 2 * rp;
            if (rA < rows)
                *(float4*)&out[(size_t)(r0 + rA) * FDIM + (tx << 2)] =
                    make_float4(lx, ly, lz, lw);
            if (rA + 1 < rows)
                *(float4*)&out[(size_t)(r0 + rA + 1) * FDIM + (tx << 2)] =
                    make_float4(hx, hy, hz, hw);
        }
    }
}

// ---------------------------------------------------------------------------
extern "C" void kernel_launch(void* const* d_in, const int* in_sizes, int n_in,
                              void* d_out, int out_size)
{
    const float* feat   = (const float*)d_in[0];
    const float* pseudo = (const float*)d_in[1];
    const int*   rowptr = (const int*)  d_in[2];
    const int*   colind = (const int*)  d_in[3];
    const float* projW  = (const float*)d_in[4];  // [L,2,2]
    const float* projb  = (const float*)d_in[5];  // [L,2]
    const float* fcW    = (const float*)d_in[6];  // [L,64,192]
    const float* mu     = (const float*)d_in[7];  // [L,3,2]
    const float* isg    = (const float*)d_in[8];  // [L,3,2]

    const int n  = in_sizes[0] / FDIM;
    const int nL = in_sizes[6] / (FDIM * KF);

    void *gp, *hap, *hbp;
    cudaGetSymbolAddress(&gp,  g_buf);
    cudaGetSymbolAddress(&hap, h_bufA);
    cudaGetSymbolAddress(&hbp, h_bufB);
    float* gbuf = (float*)gp;
    float* hbufs[2] = { (float*)hap, (float*)hbp };

    cudaFuncSetAttribute(gemm_kernel, cudaFuncAttributeMaxDynamicSharedMemorySize, GEMM_SMEM);

    const int aggGrid = (n + 7) / 8;
    const int ntiles  = (n + TROWS - 1) / TROWS;
    const int gemmGrid = ntiles < 148 ? ntiles : 148;   // persistent, 1 CTA/SM

    const float* hin = feat;
    for (int i = 0; i < nL; i++) {
        float* hout = (i == nL - 1) ? (float*)d_out : hbufs[i & 1];
        agg_kernel<<<aggGrid, 256>>>(hin, pseudo, rowptr, colind,
                                     projW + i * 4, projb + i * 2,
                                     mu + i * 6, isg + i * 6,
                                     gbuf, n);
        gemm_kernel<<<gemmGrid, 384, GEMM_SMEM>>>(gbuf, fcW + i * (FDIM * KF), hout, n);
        hin = hout;
    }
}

// round 4
// speedup vs baseline: 1.5850x; 1.0785x over previous
#include <cuda_runtime.h>
#include <cuda_bf16.h>
#include <cstddef>

// Problem constants: N=50000, DEG=32, E=N*32, F=64, K=3, DIM=2, L=3
#define MAXN 50000
#define FDIM 64
#define KF   192        // K * F
#define TILE 64         // nodes per CTA tile
#define WST_S 194       // WsT row stride (floats): 192 + 2 pad (8B-aligned, bank spread)

// smem layout (floats): gs[64][192] | WsT[64][WST_S] | w0s/w1s/w2s [8][32] | ss [8][32]
#define GS_OFF   0
#define WST_OFF  (64 * 192)
#define WAUX_OFF (WST_OFF + 64 * WST_S)
#define SMEM_FLOATS (WAUX_OFF + 4 * 256)
#define SMEM_BYTES  (SMEM_FLOATS * 4)     // 102912 B -> 2 CTAs/SM

// Scratch (device globals — no allocation in kernel_launch)
__device__ float h_bufA[(size_t)MAXN * FDIM];
__device__ float h_bufB[(size_t)MAXN * FDIM];

// Packed fp32x2 FMA (sm_103a FFMA2 — only reachable via PTX)
#define FMA_F32X2(d, a, b, c) \
    asm("fma.rn.f32x2 %0, %1, %2, %3;" : "=l"(d) : "l"(a), "l"(b), "l"(c))
#define UNPACK2(lo, hi, v) \
    asm("mov.b64 {%0, %1}, %2;" : "=f"(lo), "=f"(hi) : "l"(v))

// ---------------------------------------------------------------------------
// Fused layer kernel: per 64-node tile,
//   phase A (per warp, 8 nodes): g[r, k*64+f] = sum_e w_k(e) * h[colind[e], f]
//     written row-major to gs[r][p]  (p = k*64 + f)
//   phase B (block GEMM): out[r,f] = sum_p gs[r][p] * Wk[p][f]
//     FFMA2 packed along K: lane0 accumulates even p, lane1 odd p.
// ---------------------------------------------------------------------------
__global__ __launch_bounds__(256, 2)
void fused_layer(const float* __restrict__ h,
                 const float* __restrict__ pseudo,   // [E,2]
                 const int*   __restrict__ rowptr,   // [N+1]
                 const int*   __restrict__ colind,   // [E]
                 const float* __restrict__ pW,       // [2,2]
                 const float* __restrict__ pb,       // [2]
                 const float* __restrict__ mu,       // [K,2]
                 const float* __restrict__ isg,      // [K,2]
                 const float* __restrict__ W,        // fc_W layer: [64,192]
                 float* __restrict__ out, int n)
{
    extern __shared__ float smem[];
    float* gs  = smem + GS_OFF;     // [64][192]
    float* WsT = smem + WST_OFF;    // [64][WST_S]  WsT[f][p] = Wk[p][f]
    float* w0s = smem + WAUX_OFF;   // [8][32]
    float* w1s = w0s + 256;
    float* w2s = w0s + 512;
    int*   ss  = (int*)(w0s + 768); // [8][32]

    const int tid = threadIdx.x;
    const int wid = tid >> 5;
    const int lid = tid & 31;

    // Load transposed weights once: WsT[f][p], p = k*64+j -> W[j*192 + k*64 + f]
    for (int idx = tid; idx < 192 * 64; idx += 256) {
        const int f = idx & 63, p = idx >> 6;
        const int j = p & 63, k = p >> 6;
        WsT[f * WST_S + p] = __ldg(&W[j * 192 + k * 64 + f]);
    }

    // Scalar params
    const float W00 = pW[0], W01 = pW[1], W10 = pW[2], W11 = pW[3];
    const float b0 = pb[0], b1 = pb[1];
    const float m00 = mu[0], m01 = mu[1], m10 = mu[2], m11 = mu[3], m20 = mu[4], m21 = mu[5];
    const float s00 = isg[0]*isg[0], s01 = isg[1]*isg[1];
    const float s10 = isg[2]*isg[2], s11 = isg[3]*isg[3];
    const float s20 = isg[4]*isg[4], s21 = isg[5]*isg[5];

    const float2* __restrict__ ps2 = (const float2*)pseudo;

    const int tx = tid & 31;   // gemm cols 2tx, 2tx+1
    const int ty = tid >> 5;   // gemm rows 8ty .. +7

    const unsigned long long* wp0 = (const unsigned long long*)(WsT + (2 * tx) * WST_S);
    const unsigned long long* wp1 = (const unsigned long long*)(WsT + (2 * tx + 1) * WST_S);

    const int ntiles = (n + TILE - 1) / TILE;
    for (int tile = blockIdx.x; tile < ntiles; tile += gridDim.x) {
        const int r0 = tile * TILE;
        const int rows = min(TILE, n - r0);
        __syncthreads();   // prev gemm readers done; WsT ready on iter 0

        // ---------------- Phase A: aggregation (one warp = 8 nodes) --------
        for (int j = 0; j < 8; j++) {
            const int r = (wid << 3) + j;
            const int node = r0 + r;
            if (node >= n) break;

            const int e0 = rowptr[node], e1 = rowptr[node + 1];
            float a0x = 0.f, a0y = 0.f, a1x = 0.f, a1y = 0.f, a2x = 0.f, a2y = 0.f;

            for (int base = e0; base < e1; base += 32) {
                const int cnt = min(32, e1 - base);
                if (lid < cnt) {
                    const int e = base + lid;
                    float2 ps = __ldg(&ps2[e]);
                    float u0 = tanhf(fmaf(ps.y, W10, fmaf(ps.x, W00, b0)));
                    float u1 = tanhf(fmaf(ps.y, W11, fmaf(ps.x, W01, b1)));
                    float d0, d1;
                    d0 = u0 - m00; d1 = u1 - m01;
                    w0s[(wid << 5) + lid] = __expf(-0.5f * (d0*d0*s00 + d1*d1*s01));
                    d0 = u0 - m10; d1 = u1 - m11;
                    w1s[(wid << 5) + lid] = __expf(-0.5f * (d0*d0*s10 + d1*d1*s11));
                    d0 = u0 - m20; d1 = u1 - m21;
                    w2s[(wid << 5) + lid] = __expf(-0.5f * (d0*d0*s20 + d1*d1*s21));
                    ss[(wid << 5) + lid] = __ldg(&colind[e]);
                }
                __syncwarp();
                if (cnt == 32) {
                    #pragma unroll 8
                    for (int t = 0; t < 32; t++) {
                        const float2 hv = __ldg((const float2*)(h + (size_t)ss[(wid << 5) + t] * FDIM) + lid);
                        const float w0 = w0s[(wid << 5) + t], w1 = w1s[(wid << 5) + t], w2 = w2s[(wid << 5) + t];
                        a0x = fmaf(w0, hv.x, a0x); a0y = fmaf(w0, hv.y, a0y);
                        a1x = fmaf(w1, hv.x, a1x); a1y = fmaf(w1, hv.y, a1y);
                        a2x = fmaf(w2, hv.x, a2x); a2y = fmaf(w2, hv.y, a2y);
                    }
                } else {
                    for (int t = 0; t < cnt; t++) {
                        const float2 hv = __ldg((const float2*)(h + (size_t)ss[(wid << 5) + t] * FDIM) + lid);
                        const float w0 = w0s[(wid << 5) + t], w1 = w1s[(wid << 5) + t], w2 = w2s[(wid << 5) + t];
                        a0x = fmaf(w0, hv.x, a0x); a0y = fmaf(w0, hv.y, a0y);
                        a1x = fmaf(w1, hv.x, a1x); a1y = fmaf(w1, hv.y, a1y);
                        a2x = fmaf(w2, hv.x, a2x); a2y = fmaf(w2, hv.y, a2y);
                    }
                }
                __syncwarp();
            }
            // row-major write: gs[r][p], p = k*64 + 2lid
            float* gr = gs + r * KF + 2 * lid;
            *(float2*)(gr      ) = make_float2(a0x, a0y);
            *(float2*)(gr +  64) = make_float2(a1x, a1y);
            *(float2*)(gr + 128) = make_float2(a2x, a2y);
        }
        __syncthreads();

        // ---------------- Phase B: block GEMM (FFMA2 packed along K) -------
        const unsigned long long* gp = (const unsigned long long*)(gs + (ty << 3) * KF);
        unsigned long long acc[8][2];
        #pragma unroll
        for (int i = 0; i < 8; i++) { acc[i][0] = 0ULL; acc[i][1] = 0ULL; }

        #pragma unroll 4
        for (int pp = 0; pp < 96; pp++) {
            const unsigned long long w0 = wp0[pp];
            const unsigned long long w1 = wp1[pp];
            #pragma unroll
            for (int i = 0; i < 8; i++) {
                const unsigned long long gv = gp[i * 96 + pp];
                FMA_F32X2(acc[i][0], gv, w0, acc[i][0]);
                FMA_F32X2(acc[i][1], gv, w1, acc[i][1]);
            }
        }

        #pragma unroll
        for (int i = 0; i < 8; i++) {
            const int r = (ty << 3) + i;
            if (r < rows) {
                float e0, o0, e1, o1;
                UNPACK2(e0, o0, acc[i][0]);
                UNPACK2(e1, o1, acc[i][1]);
                *(float2*)&out[(size_t)(r0 + r) * FDIM + 2 * tx] =
                    make_float2(e0 + o0, e1 + o1);
            }
        }
    }
}

// ---------------------------------------------------------------------------
extern "C" void kernel_launch(void* const* d_in, const int* in_sizes, int n_in,
                              void* d_out, int out_size)
{
    const float* feat   = (const float*)d_in[0];
    const float* pseudo = (const float*)d_in[1];
    const int*   rowptr = (const int*)  d_in[2];
    const int*   colind = (const int*)  d_in[3];
    const float* projW  = (const float*)d_in[4];  // [L,2,2]
    const float* projb  = (const float*)d_in[5];  // [L,2]
    const float* fcW    = (const float*)d_in[6];  // [L,64,192]
    const float* mu     = (const float*)d_in[7];  // [L,3,2]
    const float* isg    = (const float*)d_in[8];  // [L,3,2]

    const int n  = in_sizes[0] / FDIM;
    const int nL = in_sizes[6] / (FDIM * KF);

    void *hap, *hbp;
    cudaGetSymbolAddress(&hap, h_bufA);
    cudaGetSymbolAddress(&hbp, h_bufB);
    float* hbufs[2] = { (float*)hap, (float*)hbp };

    cudaFuncSetAttribute(fused_layer, cudaFuncAttributeMaxDynamicSharedMemorySize, SMEM_BYTES);

    const int ntiles = (n + TILE - 1) / TILE;
    const int grid = ntiles < 296 ? ntiles : 296;   // 2 CTAs/SM persistent

    const float* hin = feat;
    for (int i = 0; i < nL; i++) {
        float* hout = (i == nL - 1) ? (float*)d_out : hbufs[i & 1];
        fused_layer<<<grid, 256, SMEM_BYTES>>>(hin, pseudo, rowptr, colind,
                                               projW + i * 4, projb + i * 2,
                                               mu + i * 6, isg + i * 6,
                                               fcW + i * (FDIM * KF), hout, n);
        hin = hout;
    }
}